// round 15
// baseline (speedup 1.0000x reference)
#include <cuda_runtime.h>
#include <cstdint>

#define ROWS 131072
#define COLS 256
#define NM   128
#define WPB  8                    // warps per block (one row per warp)
#define THREADS (WPB * 32)

__device__ __forceinline__ void ldg256(const float* p, unsigned v[8]) {
    asm volatile("ld.global.v8.b32 {%0,%1,%2,%3,%4,%5,%6,%7}, [%8];"
                 : "=r"(v[0]), "=r"(v[1]), "=r"(v[2]), "=r"(v[3]),
                   "=r"(v[4]), "=r"(v[5]), "=r"(v[6]), "=r"(v[7])
                 : "l"(p));
}

__device__ __forceinline__ void stg256(float* p, const unsigned v[8]) {
    asm volatile("st.global.v8.b32 [%0], {%1,%2,%3,%4,%5,%6,%7,%8};"
                 :: "l"(p),
                    "r"(v[0]), "r"(v[1]), "r"(v[2]), "r"(v[3]),
                    "r"(v[4]), "r"(v[5]), "r"(v[6]), "r"(v[7])
                 : "memory");
}

// Output = concat(masked_data, masked_indices, unmasked_data, unmasked_indices),
// each [ROWS, 128] row-major f32.
//
// Per-row algorithm (no sort needed — rows are permutations of 0..255):
//   1. Read the first 128 perm entries (the masked set).
//   2. Build a 256-bit membership bitmap in registers, combine with REDUX.OR.
//   3. Rank each column by prefix-popcount; scatter indices/data to their
//      sorted positions in an SMEM stage.
//   4. Write all four segments with 256-bit coalesced stores.
__global__ void __launch_bounds__(THREADS)
masker_kernel(const float* __restrict__ x,
              const int*   __restrict__ perm,
              float* __restrict__ out) {
    const int warp_id = threadIdx.x >> 5;
    const int lane    = threadIdx.x & 31;
    const int row     = blockIdx.x * WPB + warp_id;

    __shared__ __align__(16) float stage[WPB][3 * NM];   // [mi | ud | ui]

    // ---- global loads, front-batched ----
    const int4* prow = reinterpret_cast<const int4*>(perm + (size_t)row * COLS);
    int4 mh = prow[lane];                       // masked half (first 128 entries)
    unsigned xv[8];                             // x cols [8*lane, 8*lane+8)
    ldg256(x + (size_t)row * COLS + 8 * lane, xv);

    // ---- 256-bit membership bitmap in registers ----
    unsigned local[8] = {0, 0, 0, 0, 0, 0, 0, 0};
    {
        const int vs[4] = {mh.x, mh.y, mh.z, mh.w};
#pragma unroll
        for (int j = 0; j < 4; j++) {
            const int v = vs[j];
            const unsigned b = 1u << (v & 31);
            const int w = v >> 5;
#pragma unroll
            for (int ww = 0; ww < 8; ww++)
                local[ww] |= (w == ww) ? b : 0u;
        }
    }
    unsigned mask[8];
#pragma unroll
    for (int w = 0; w < 8; w++)
        mask[w] = __reduce_or_sync(0xffffffffu, local[w]);

    int base[8];
    int acc = 0;
#pragma unroll
    for (int w = 0; w < 8; w++) { base[w] = acc; acc += __popc(mask[w]); }

    // lane owns cols 8l..8l+7, all inside word w = lane>>2: single select tree
    const bool s2 = (lane & 16) != 0;
    const bool s1 = (lane & 8)  != 0;
    const bool s0 = (lane & 4)  != 0;
    const unsigned mAB = s1 ? (s0 ? mask[3] : mask[2]) : (s0 ? mask[1] : mask[0]);
    const unsigned mCD = s1 ? (s0 ? mask[7] : mask[6]) : (s0 ? mask[5] : mask[4]);
    const unsigned mw  = s2 ? mCD : mAB;
    const int bAB = s1 ? (s0 ? base[3] : base[2]) : (s0 ? base[1] : base[0]);
    const int bCD = s1 ? (s0 ? base[7] : base[6]) : (s0 ? base[5] : base[4]);
    const int bw  = s2 ? bCD : bAB;

    float* smi = stage[warp_id];
    float* sud = stage[warp_id] + NM;
    float* sui = stage[warp_id] + 2 * NM;

    // ---- rank + scatter into stage, x straight from registers ----
#pragma unroll
    for (int j = 0; j < 8; j++) {
        const int c   = 8 * lane + j;
        const int bit = c & 31;
        const int mrank = bw + __popc(mw & ((1u << bit) - 1u));
        if ((mw >> bit) & 1u) {
            smi[mrank] = (float)c;
        } else {
            const int urank = c - mrank;
            sud[urank] = __uint_as_float(xv[j]);
            sui[urank] = (float)c;
        }
    }
    __syncwarp();

    // ---- 256-bit write-out: each lane does two STG.256 ----
    // lanes 0-15:  mi chunk idx, then ui chunk idx
    // lanes 16-31: ud chunk idx, then zeros chunk idx
    const size_t seg = (size_t)ROWS * NM;
    const int half = lane >> 4;          // 0 or 1
    const int idx  = lane & 15;          // chunk of 8 floats, 0..15

    float* rowbase = out + (size_t)row * NM;
    float* dst1 = (half ? rowbase + 2 * seg : rowbase + seg)     + 8 * idx;
    float* src1 = (half ? sud : smi) + 8 * idx;
    float* dst2 = (half ? rowbase           : rowbase + 3 * seg) + 8 * idx;

    unsigned v1[8];
#pragma unroll
    for (int j = 0; j < 8; j++) v1[j] = __float_as_uint(src1[j]);
    stg256(dst1, v1);

    unsigned v2[8];
    if (half) {
#pragma unroll
        for (int j = 0; j < 8; j++) v2[j] = 0u;            // masked_data zeros
    } else {
#pragma unroll
        for (int j = 0; j < 8; j++) v2[j] = __float_as_uint(sui[8 * idx + j]);
    }
    stg256(dst2, v2);
}

extern "C" void kernel_launch(void* const* d_in, const int* in_sizes, int n_in,
                              void* d_out, int out_size) {
    const float* x    = (const float*)d_in[0];
    const int*   perm = (const int*)d_in[1];
    float* out = (float*)d_out;

    masker_kernel<<<ROWS / WPB, THREADS>>>(x, perm, out);
}

// round 16
// speedup vs baseline: 1.0098x; 1.0098x over previous
#include <cuda_runtime.h>
#include <cstdint>

#define ROWS 131072
#define COLS 256
#define NM   128
#define WPB  8                    // warps per block (one row per warp)
#define THREADS (WPB * 32)

__device__ __forceinline__ void ldg256(const float* p, unsigned v[8]) {
    asm volatile("ld.global.v8.b32 {%0,%1,%2,%3,%4,%5,%6,%7}, [%8];"
                 : "=r"(v[0]), "=r"(v[1]), "=r"(v[2]), "=r"(v[3]),
                   "=r"(v[4]), "=r"(v[5]), "=r"(v[6]), "=r"(v[7])
                 : "l"(p));
}

__device__ __forceinline__ void stg256(float* p, const unsigned v[8]) {
    asm volatile("st.global.v8.b32 [%0], {%1,%2,%3,%4,%5,%6,%7,%8};"
                 :: "l"(p),
                    "r"(v[0]), "r"(v[1]), "r"(v[2]), "r"(v[3]),
                    "r"(v[4]), "r"(v[5]), "r"(v[6]), "r"(v[7])
                 : "memory");
}

__device__ __forceinline__ uint32_t smem_u32(const void* p) {
    uint32_t a;
    asm("{ .reg .u64 t; cvta.to.shared.u64 t, %1; cvt.u32.u64 %0, t; }"
        : "=r"(a) : "l"(p));
    return a;
}

__device__ __forceinline__ void bulk_store(void* gmem, uint32_t smem, uint32_t bytes) {
    asm volatile("cp.async.bulk.global.shared::cta.bulk_group [%0], [%1], %2;"
                 :: "l"(gmem), "r"(smem), "r"(bytes) : "memory");
}

// Output = concat(masked_data, masked_indices, unmasked_data, unmasked_indices),
// each [ROWS, 128] row-major f32.
// Block-wide 4KB staging per segment -> three 4KB TMA bulk stores per block.
__global__ void __launch_bounds__(THREADS)
masker_kernel(const float* __restrict__ x,
              const int*   __restrict__ perm,
              float* __restrict__ out) {
    const int warp_id = threadIdx.x >> 5;
    const int lane    = threadIdx.x & 31;
    const int row0    = blockIdx.x * WPB;
    const int row     = row0 + warp_id;

    // Segment-major block staging: each array is a contiguous 4KB span.
    __shared__ __align__(16) float smi_s[WPB][NM];
    __shared__ __align__(16) float sud_s[WPB][NM];
    __shared__ __align__(16) float sui_s[WPB][NM];

    // ---- global loads, front-batched ----
    const int4* prow = reinterpret_cast<const int4*>(perm + (size_t)row * COLS);
    int4 mh = prow[lane];                       // masked half (first 128 entries)
    unsigned xv[8];                             // x cols [8*lane, 8*lane+8)
    ldg256(x + (size_t)row * COLS + 8 * lane, xv);

    // ---- 256-bit membership bitmap in registers ----
    unsigned local[8] = {0, 0, 0, 0, 0, 0, 0, 0};
    {
        const int vs[4] = {mh.x, mh.y, mh.z, mh.w};
#pragma unroll
        for (int j = 0; j < 4; j++) {
            const int v = vs[j];
            const unsigned b = 1u << (v & 31);
            const int w = v >> 5;
#pragma unroll
            for (int ww = 0; ww < 8; ww++)
                local[ww] |= (w == ww) ? b : 0u;
        }
    }
    unsigned mask[8];
#pragma unroll
    for (int w = 0; w < 8; w++)
        mask[w] = __reduce_or_sync(0xffffffffu, local[w]);

    int base[8];
    int acc = 0;
#pragma unroll
    for (int w = 0; w < 8; w++) { base[w] = acc; acc += __popc(mask[w]); }

    // lane owns cols 8l..8l+7, all inside word w = lane>>2: single select tree
    const bool s2 = (lane & 16) != 0;
    const bool s1 = (lane & 8)  != 0;
    const bool s0 = (lane & 4)  != 0;
    const unsigned mAB = s1 ? (s0 ? mask[3] : mask[2]) : (s0 ? mask[1] : mask[0]);
    const unsigned mCD = s1 ? (s0 ? mask[7] : mask[6]) : (s0 ? mask[5] : mask[4]);
    const unsigned mw  = s2 ? mCD : mAB;
    const int bAB = s1 ? (s0 ? base[3] : base[2]) : (s0 ? base[1] : base[0]);
    const int bCD = s1 ? (s0 ? base[7] : base[6]) : (s0 ? base[5] : base[4]);
    const int bw  = s2 ? bCD : bAB;

    float* smi = smi_s[warp_id];
    float* sud = sud_s[warp_id];
    float* sui = sui_s[warp_id];

    // ---- rank + scatter into stage, x straight from registers ----
#pragma unroll
    for (int j = 0; j < 8; j++) {
        const int c   = 8 * lane + j;
        const int bit = c & 31;
        const int mrank = bw + __popc(mw & ((1u << bit) - 1u));
        if ((mw >> bit) & 1u) {
            smi[mrank] = (float)c;
        } else {
            const int urank = c - mrank;
            sud[urank] = __uint_as_float(xv[j]);
            sui[urank] = (float)c;
        }
    }

    // ---- masked_data zeros: register-direct STG.256, lanes 0-15 ----
    if (lane < 16) {
        unsigned z[8] = {0, 0, 0, 0, 0, 0, 0, 0};
        stg256(out + (size_t)row * NM + 8 * lane, z);
    }

    __syncthreads();

    // ---- three 4KB bulk stores per block (page-sequential per segment) ----
    if (threadIdx.x == 0) {
        asm volatile("fence.proxy.async.shared::cta;" ::: "memory");
        const size_t seg = (size_t)ROWS * NM;
        const size_t off = (size_t)row0 * NM;
        bulk_store(out + seg     + off, smem_u32(smi_s), WPB * NM * 4);
        bulk_store(out + 2 * seg + off, smem_u32(sud_s), WPB * NM * 4);
        bulk_store(out + 3 * seg + off, smem_u32(sui_s), WPB * NM * 4);
        asm volatile("cp.async.bulk.commit_group;" ::: "memory");
        asm volatile("cp.async.bulk.wait_group 0;" ::: "memory");
    }
}

extern "C" void kernel_launch(void* const* d_in, const int* in_sizes, int n_in,
                              void* d_out, int out_size) {
    const float* x    = (const float*)d_in[0];
    const int*   perm = (const int*)d_in[1];
    float* out = (float*)d_out;

    masker_kernel<<<ROWS / WPB, THREADS>>>(x, perm, out);
}